// round 1
// baseline (speedup 1.0000x reference)
#include <cuda_runtime.h>
#include <cuda_bf16.h>
#include <math.h>

#define NN 50000
#define EE 600000
#define HH 128
#define GG 128
#define LL 3
#define OUTD 16

// ---------------- scratch (device globals; no allocation) ----------------
__device__ __align__(256) float g_h[(size_t)NN * HH];    // node features
__device__ __align__(256) float g_tmp[(size_t)NN * HH];  // dense GEMM output
__device__ __align__(256) float g_acc[(size_t)NN * HH];  // scatter accumulator
__device__ __align__(256) float g_gate[NN];              // gate logits
__device__ __align__(256) float g_emb[GG * HH];          // graph embeddings

// ---------------- GEMM: C[n,128] = A[n,128] @ W[128,128] + b (opt relu) ----
// 64-row block tile, 256 threads, each thread 8 rows x 4 cols.
// smem: W 64KB (k-major, matches global layout) + A tile 32KB = 96KB dynamic.
__global__ void gemm128_kernel(const float* __restrict__ A,
                               const float* __restrict__ W,
                               const float* __restrict__ bias,
                               float* __restrict__ C,
                               int nrows, int doRelu)
{
    extern __shared__ float sm[];
    float4* Ws4 = (float4*)sm;            // 128*32 float4
    float*  As  = sm + 128 * 128;         // 64*128 floats
    float4* As4 = (float4*)As;

    int tid = threadIdx.x;

    const float4* Wg4 = (const float4*)W;
#pragma unroll
    for (int i = tid; i < 4096; i += 256) Ws4[i] = Wg4[i];

    int rowBase = blockIdx.x << 6;
    const float4* Ag4 = (const float4*)A;
#pragma unroll
    for (int i = tid; i < 2048; i += 256) {
        int r = i >> 5;
        int gr = rowBase + r;
        As4[i] = (gr < nrows) ? Ag4[(size_t)gr * 32 + (i & 31)]
                              : make_float4(0.f, 0.f, 0.f, 0.f);
    }
    __syncthreads();

    int tx = tid & 31;        // col group: cols [tx*4, tx*4+3]
    int ty = tid >> 5;        // row group: rows [ty*8, ty*8+7]
    int r0 = ty << 3;

    float4 bv = ((const float4*)bias)[tx];
    float4 acc[8];
#pragma unroll
    for (int i = 0; i < 8; i++) acc[i] = bv;

#pragma unroll 8
    for (int k = 0; k < 128; k++) {
        float4 wv = Ws4[(k << 5) + tx];
#pragma unroll
        for (int i = 0; i < 8; i++) {
            float a = As[((r0 + i) << 7) + k];
            acc[i].x += a * wv.x;
            acc[i].y += a * wv.y;
            acc[i].z += a * wv.z;
            acc[i].w += a * wv.w;
        }
    }

    float4* Cg4 = (float4*)C;
#pragma unroll
    for (int i = 0; i < 8; i++) {
        int gr = rowBase + r0 + i;
        if (gr < nrows) {
            float4 v = acc[i];
            if (doRelu) {
                v.x = fmaxf(v.x, 0.f); v.y = fmaxf(v.y, 0.f);
                v.z = fmaxf(v.z, 0.f); v.w = fmaxf(v.w, 0.f);
            }
            Cg4[(size_t)gr * 32 + tx] = v;
        }
    }
}

// ---------------- SpMM scatter: acc[row[e]] += w[e] * hn[col[e]] ----------
// one warp per edge; float4 lanes; vector reduction atomics (no return).
__global__ void spmm_scatter_kernel(const float* __restrict__ hn,
                                    const float* __restrict__ ew,
                                    const int* __restrict__ er,
                                    const int* __restrict__ ec,
                                    float* __restrict__ acc)
{
    int idx = blockIdx.x * blockDim.x + threadIdx.x;
    int e = idx >> 5;
    int lane = idx & 31;
    if (e >= EE) return;
    int r = er[e];
    int c = ec[e];
    float w = ew[e];
    float4 v = ((const float4*)hn)[(size_t)c * 32 + lane];
    v.x *= w; v.y *= w; v.z *= w; v.w *= w;
    float* dst = acc + (size_t)r * 128 + lane * 4;
    asm volatile("red.global.add.v4.f32 [%0], {%1,%2,%3,%4};"
                 :: "l"(dst), "f"(v.x), "f"(v.y), "f"(v.z), "f"(v.w)
                 : "memory");
}

// ---------------- BN(eval) + ReLU + residual: h += relu(affine(acc)) ------
__global__ void bn_relu_res_kernel(float* __restrict__ h,
                                   const float* __restrict__ acc,
                                   const float* __restrict__ gamma,
                                   const float* __restrict__ beta,
                                   const float* __restrict__ mean,
                                   const float* __restrict__ var)
{
    __shared__ float sc[128], sh[128];
    if (threadIdx.x < 128) {
        int j = threadIdx.x;
        float s = gamma[j] * rsqrtf(var[j] + 1e-5f);
        sc[j] = s;
        sh[j] = beta[j] - mean[j] * s;
    }
    __syncthreads();
    int total = NN * 32;
    int stride = gridDim.x * blockDim.x;
    for (int t = blockIdx.x * blockDim.x + threadIdx.x; t < total; t += stride) {
        int j4 = (t & 31) * 4;
        float4 a = ((const float4*)acc)[t];
        float4 hv = ((float4*)h)[t];
        hv.x += fmaxf(fmaf(a.x, sc[j4 + 0], sh[j4 + 0]), 0.f);
        hv.y += fmaxf(fmaf(a.y, sc[j4 + 1], sh[j4 + 1]), 0.f);
        hv.z += fmaxf(fmaf(a.z, sc[j4 + 2], sh[j4 + 2]), 0.f);
        hv.w += fmaxf(fmaf(a.w, sc[j4 + 3], sh[j4 + 3]), 0.f);
        ((float4*)h)[t] = hv;
    }
}

// ---------------- gate logits: g[i] = h[i] . gate_W + gate_b -------------
__global__ void gate_kernel(const float* __restrict__ h,
                            const float* __restrict__ gw,
                            const float* __restrict__ gb,
                            float* __restrict__ g)
{
    int idx = blockIdx.x * blockDim.x + threadIdx.x;
    int node = idx >> 5;
    int lane = idx & 31;
    if (node >= NN) return;
    float4 hv = ((const float4*)h)[(size_t)node * 32 + lane];
    float4 wv = ((const float4*)gw)[lane];
    float d = hv.x * wv.x + hv.y * wv.y + hv.z * wv.z + hv.w * wv.w;
#pragma unroll
    for (int off = 16; off; off >>= 1) d += __shfl_xor_sync(0xFFFFFFFFu, d, off);
    if (lane == 0) g[node] = d + gb[0];
}

// ---------------- per-graph softmax-attention pooling --------------------
// batch is sorted: block b binary-searches its node range; no global atomics.
__global__ void pool_kernel(const float* __restrict__ h,
                            const float* __restrict__ g,
                            const int* __restrict__ batch,
                            float* __restrict__ emb)
{
    int b = blockIdx.x;
    int tid = threadIdx.x;  // 128 threads

    int lo = 0, hi = NN;
    while (lo < hi) { int mid = (lo + hi) >> 1; if (batch[mid] < b) lo = mid + 1; else hi = mid; }
    int start = lo;
    hi = NN;
    while (lo < hi) { int mid = (lo + hi) >> 1; if (batch[mid] < b + 1) lo = mid + 1; else hi = mid; }
    int end = lo;

    __shared__ float red[128];
    __shared__ float coef[128];

    // max
    float lm = -3.402823466e38f;
    for (int i = start + tid; i < end; i += 128) lm = fmaxf(lm, g[i]);
    red[tid] = lm; __syncthreads();
    for (int s = 64; s; s >>= 1) { if (tid < s) red[tid] = fmaxf(red[tid], red[tid + s]); __syncthreads(); }
    float m = red[0]; __syncthreads();

    // sum exp
    float ls = 0.f;
    for (int i = start + tid; i < end; i += 128) ls += expf(g[i] - m);
    red[tid] = ls; __syncthreads();
    for (int s = 64; s; s >>= 1) { if (tid < s) red[tid] += red[tid + s]; __syncthreads(); }
    float inv = 1.f / (red[0] + 1e-10f); __syncthreads();

    // weighted sum (thread tid owns feature tid)
    float acc = 0.f;
    for (int base = start; base < end; base += 128) {
        int i = base + tid;
        coef[tid] = (i < end) ? expf(g[i] - m) * inv : 0.f;
        __syncthreads();
        int cnt = min(128, end - base);
        for (int ii = 0; ii < cnt; ii++)
            acc += coef[ii] * h[(size_t)(base + ii) * 128 + tid];
        __syncthreads();
    }
    emb[b * 128 + tid] = acc;
}

// ---------------- head MLP: relu(emb@W1+b1)@W2+b2 ------------------------
__global__ void head_kernel(const float* __restrict__ emb,
                            const float* __restrict__ W1,
                            const float* __restrict__ b1,
                            const float* __restrict__ W2,
                            const float* __restrict__ b2,
                            float* __restrict__ out)
{
    int b = blockIdx.x;
    int tid = threadIdx.x;  // 128
    __shared__ float se[128], st[128];
    se[tid] = emb[b * 128 + tid];
    __syncthreads();
    float acc = b1[tid];
#pragma unroll 8
    for (int k = 0; k < 128; k++) acc += se[k] * W1[k * 128 + tid];
    st[tid] = fmaxf(acc, 0.f);
    __syncthreads();
    if (tid < OUTD) {
        float o = b2[tid];
#pragma unroll 8
        for (int k = 0; k < 128; k++) o += st[k] * W2[k * OUTD + tid];
        out[b * OUTD + tid] = o;
    }
}

// ---------------- launcher ----------------------------------------------
extern "C" void kernel_launch(void* const* d_in, const int* in_sizes, int n_in,
                              void* d_out, int out_size)
{
    const float* x        = (const float*)d_in[0];
    const float* edge_w   = (const float*)d_in[1];
    const float* W_in     = (const float*)d_in[2];
    const float* b_in     = (const float*)d_in[3];
    const float* conv_W   = (const float*)d_in[4];
    const float* conv_b   = (const float*)d_in[5];
    const float* bn_gamma = (const float*)d_in[6];
    const float* bn_beta  = (const float*)d_in[7];
    const float* bn_mean  = (const float*)d_in[8];
    const float* bn_var   = (const float*)d_in[9];
    const float* gate_W   = (const float*)d_in[10];
    const float* gate_b   = (const float*)d_in[11];
    const float* head_W1  = (const float*)d_in[12];
    const float* head_b1  = (const float*)d_in[13];
    const float* head_W2  = (const float*)d_in[14];
    const float* head_b2  = (const float*)d_in[15];
    const int*   er       = (const int*)d_in[16];
    const int*   ec       = (const int*)d_in[17];
    const int*   batch    = (const int*)d_in[18];
    float* out = (float*)d_out;

    float *h, *tmp, *acc, *gate, *emb;
    cudaGetSymbolAddress((void**)&h,   g_h);
    cudaGetSymbolAddress((void**)&tmp, g_tmp);
    cudaGetSymbolAddress((void**)&acc, g_acc);
    cudaGetSymbolAddress((void**)&gate, g_gate);
    cudaGetSymbolAddress((void**)&emb, g_emb);

    cudaFuncSetAttribute(gemm128_kernel,
                         cudaFuncAttributeMaxDynamicSharedMemorySize, 98304);

    const int gemmGrid = (NN + 63) / 64;           // 782
    const int scatGrid = (EE * 32 + 255) / 256;    // 75000
    const int gateGrid = (NN * 32 + 255) / 256;    // 6250

    // input projection + relu
    gemm128_kernel<<<gemmGrid, 256, 98304>>>(x, W_in, b_in, h, NN, 1);

    for (int l = 0; l < LL; l++) {
        gemm128_kernel<<<gemmGrid, 256, 98304>>>(h, conv_W + (size_t)l * HH * HH,
                                                 conv_b + l * HH, tmp, NN, 0);
        cudaMemsetAsync(acc, 0, (size_t)NN * HH * sizeof(float));
        spmm_scatter_kernel<<<scatGrid, 256>>>(tmp, edge_w, er, ec, acc);
        bn_relu_res_kernel<<<1480, 256>>>(h, acc,
                                          bn_gamma + l * HH, bn_beta + l * HH,
                                          bn_mean + l * HH, bn_var + l * HH);
    }

    gate_kernel<<<gateGrid, 256>>>(h, gate_W, gate_b, gate);
    pool_kernel<<<GG, 128>>>(h, gate, batch, emb);
    head_kernel<<<GG, 128>>>(emb, head_W1, head_b1, head_W2, head_b2, out);
}

// round 2
// speedup vs baseline: 1.2913x; 1.2913x over previous
#include <cuda_runtime.h>
#include <cuda_bf16.h>
#include <math.h>
#include <stdint.h>

#define NN 50000
#define EE 600000
#define HH 128
#define GG 128
#define LL 3
#define OUTD 16

// ---------------- scratch (device globals; no allocation) ----------------
__device__ __align__(256) float g_h[(size_t)NN * HH];    // node features
__device__ __align__(256) float g_tmp[(size_t)NN * HH];  // dense GEMM output
__device__ __align__(256) float g_acc[(size_t)NN * HH];  // scatter accumulator
__device__ __align__(256) float g_gate[NN];              // gate logits
__device__ __align__(256) float g_emb[GG * HH];          // graph embeddings
__device__ __align__(256) float g_m[GG];                 // per-graph max
__device__ __align__(256) float g_invs[GG];              // per-graph 1/sumexp

// ---------------- tf32 helpers ----------------
__device__ __forceinline__ float to_tf32(float x) {
    uint32_t u;
    asm("cvt.rna.tf32.f32 %0, %1;" : "=r"(u) : "f"(x));
    return __uint_as_float(u);
}

__device__ __forceinline__ void mma_tf32(float* c, const uint32_t* a, const uint32_t* b) {
    asm volatile(
        "mma.sync.aligned.m16n8k8.row.col.f32.tf32.tf32.f32 "
        "{%0,%1,%2,%3},{%4,%5,%6,%7},{%8,%9},{%0,%1,%2,%3};"
        : "+f"(c[0]), "+f"(c[1]), "+f"(c[2]), "+f"(c[3])
        : "r"(a[0]), "r"(a[1]), "r"(a[2]), "r"(a[3]), "r"(b[0]), "r"(b[1]));
}

// ---------------- TF32 GEMM: C[n,128] = A[n,128] @ W[128,128] + b --------
// Block tile: 128 rows x 128 cols, K=128 single stage.
// smem: W padded [128][132] + A padded [128][132] = 135168 B.
// 8 warps: warp (wm=wid>>1, wn=wid&1) computes rows wm*32..+31, cols wn*64..+63
// as 2 x 8 m16n8k8 tf32 MMA tiles. Fragment LDS is bank-conflict-free
// (bank = 4*(lane>>2)+(lane&3), bijective) thanks to the 132-stride pad.
#define SPAD 132
__global__ void __launch_bounds__(256, 1)
gemm_tf32_kernel(const float* __restrict__ A,
                 const float* __restrict__ W,
                 const float* __restrict__ bias,
                 float* __restrict__ C,
                 int nrows, int doRelu)
{
    extern __shared__ float sm[];
    float* Ws = sm;                 // 128*132
    float* As = sm + 128 * SPAD;    // 128*132

    int tid = threadIdx.x;
    int rowBase = blockIdx.x << 7;

    // stage W (k-major [128][128]) -> Ws[k][n], tf32-converted
    const float4* Wg4 = (const float4*)W;
#pragma unroll
    for (int i = tid; i < 4096; i += 256) {
        int r = i >> 5, c4 = (i & 31) << 2;
        float4 v = Wg4[i];
        v.x = to_tf32(v.x); v.y = to_tf32(v.y);
        v.z = to_tf32(v.z); v.w = to_tf32(v.w);
        *(float4*)(Ws + r * SPAD + c4) = v;
    }
    // stage A tile -> As[m][k], tf32-converted
    const float4* Ag4 = (const float4*)A;
#pragma unroll
    for (int i = tid; i < 4096; i += 256) {
        int r = i >> 5, c4 = (i & 31) << 2;
        int gr = rowBase + r;
        float4 v = (gr < nrows) ? Ag4[(size_t)gr * 32 + (i & 31)]
                                : make_float4(0.f, 0.f, 0.f, 0.f);
        v.x = to_tf32(v.x); v.y = to_tf32(v.y);
        v.z = to_tf32(v.z); v.w = to_tf32(v.w);
        *(float4*)(As + r * SPAD + c4) = v;
    }
    __syncthreads();

    int wid = tid >> 5, lane = tid & 31;
    int wm = wid >> 1;            // 0..3 -> rows wm*32
    int wn = wid & 1;             // 0..1 -> cols wn*64
    int gq = lane >> 2;           // group id 0..7
    int tq = lane & 3;            // thread-in-group 0..3

    float acc[2][8][4];
#pragma unroll
    for (int mi = 0; mi < 2; mi++)
#pragma unroll
        for (int ni = 0; ni < 8; ni++)
#pragma unroll
            for (int j = 0; j < 4; j++) acc[mi][ni][j] = 0.f;

#pragma unroll
    for (int k0 = 0; k0 < 128; k0 += 8) {
        uint32_t a[2][4];
#pragma unroll
        for (int mi = 0; mi < 2; mi++) {
            int R = (wm << 5) + (mi << 4);
            a[mi][0] = __float_as_uint(As[(R + gq) * SPAD + k0 + tq]);
            a[mi][1] = __float_as_uint(As[(R + gq + 8) * SPAD + k0 + tq]);
            a[mi][2] = __float_as_uint(As[(R + gq) * SPAD + k0 + tq + 4]);
            a[mi][3] = __float_as_uint(As[(R + gq + 8) * SPAD + k0 + tq + 4]);
        }
        uint32_t b[8][2];
#pragma unroll
        for (int ni = 0; ni < 8; ni++) {
            int Cn = (wn << 6) + (ni << 3);
            b[ni][0] = __float_as_uint(Ws[(k0 + tq) * SPAD + Cn + gq]);
            b[ni][1] = __float_as_uint(Ws[(k0 + tq + 4) * SPAD + Cn + gq]);
        }
#pragma unroll
        for (int mi = 0; mi < 2; mi++)
#pragma unroll
            for (int ni = 0; ni < 8; ni++)
                mma_tf32(acc[mi][ni], a[mi], b[ni]);
    }

    // epilogue: c0=(g,2t) c1=(g,2t+1) c2=(g+8,2t) c3=(g+8,2t+1)
#pragma unroll
    for (int mi = 0; mi < 2; mi++) {
        int r0 = rowBase + (wm << 5) + (mi << 4) + gq;
#pragma unroll
        for (int ni = 0; ni < 8; ni++) {
            int col = (wn << 6) + (ni << 3) + (tq << 1);
            float b0 = bias[col], b1 = bias[col + 1];
            float v0 = acc[mi][ni][0] + b0, v1 = acc[mi][ni][1] + b1;
            float v2 = acc[mi][ni][2] + b0, v3 = acc[mi][ni][3] + b1;
            if (doRelu) {
                v0 = fmaxf(v0, 0.f); v1 = fmaxf(v1, 0.f);
                v2 = fmaxf(v2, 0.f); v3 = fmaxf(v3, 0.f);
            }
            if (r0 < nrows)     *(float2*)(C + (size_t)r0 * 128 + col)       = make_float2(v0, v1);
            if (r0 + 8 < nrows) *(float2*)(C + (size_t)(r0 + 8) * 128 + col) = make_float2(v2, v3);
        }
    }
}

// ---------------- SpMM scatter: acc[row[e]] += w[e] * hn[col[e]] ----------
__global__ void spmm_scatter_kernel(const float* __restrict__ hn,
                                    const float* __restrict__ ew,
                                    const int* __restrict__ er,
                                    const int* __restrict__ ec,
                                    float* __restrict__ acc)
{
    int idx = blockIdx.x * blockDim.x + threadIdx.x;
    int e = idx >> 5;
    int lane = idx & 31;
    if (e >= EE) return;
    int r = er[e];
    int c = ec[e];
    float w = ew[e];
    float4 v = ((const float4*)hn)[(size_t)c * 32 + lane];
    v.x *= w; v.y *= w; v.z *= w; v.w *= w;
    float* dst = acc + (size_t)r * 128 + lane * 4;
    asm volatile("red.global.add.v4.f32 [%0], {%1,%2,%3,%4};"
                 :: "l"(dst), "f"(v.x), "f"(v.y), "f"(v.z), "f"(v.w)
                 : "memory");
}

// ---------------- BN(eval) + ReLU + residual ------------------------------
__global__ void bn_relu_res_kernel(float* __restrict__ h,
                                   const float* __restrict__ acc,
                                   const float* __restrict__ gamma,
                                   const float* __restrict__ beta,
                                   const float* __restrict__ mean,
                                   const float* __restrict__ var)
{
    __shared__ float sc[128], sh[128];
    if (threadIdx.x < 128) {
        int j = threadIdx.x;
        float s = gamma[j] * rsqrtf(var[j] + 1e-5f);
        sc[j] = s;
        sh[j] = beta[j] - mean[j] * s;
    }
    __syncthreads();
    int total = NN * 32;
    int stride = gridDim.x * blockDim.x;
    for (int t = blockIdx.x * blockDim.x + threadIdx.x; t < total; t += stride) {
        int j4 = (t & 31) * 4;
        float4 a = ((const float4*)acc)[t];
        float4 hv = ((float4*)h)[t];
        hv.x += fmaxf(fmaf(a.x, sc[j4 + 0], sh[j4 + 0]), 0.f);
        hv.y += fmaxf(fmaf(a.y, sc[j4 + 1], sh[j4 + 1]), 0.f);
        hv.z += fmaxf(fmaf(a.z, sc[j4 + 2], sh[j4 + 2]), 0.f);
        hv.w += fmaxf(fmaf(a.w, sc[j4 + 3], sh[j4 + 3]), 0.f);
        ((float4*)h)[t] = hv;
    }
}

// ---------------- gate logits: g[i] = h[i] . gate_W + gate_b -------------
__global__ void gate_kernel(const float* __restrict__ h,
                            const float* __restrict__ gw,
                            const float* __restrict__ gb,
                            float* __restrict__ g)
{
    int idx = blockIdx.x * blockDim.x + threadIdx.x;
    int node = idx >> 5;
    int lane = idx & 31;
    if (node >= NN) return;
    float4 hv = ((const float4*)h)[(size_t)node * 32 + lane];
    float4 wv = ((const float4*)gw)[lane];
    float d = hv.x * wv.x + hv.y * wv.y + hv.z * wv.z + hv.w * wv.w;
#pragma unroll
    for (int off = 16; off; off >>= 1) d += __shfl_xor_sync(0xFFFFFFFFu, d, off);
    if (lane == 0) g[node] = d + gb[0];
}

// ---------------- per-graph softmax stats (max, 1/sumexp) ----------------
__global__ void seg_stats_kernel(const float* __restrict__ g,
                                 const int* __restrict__ batch,
                                 float* __restrict__ mOut,
                                 float* __restrict__ invOut)
{
    int b = blockIdx.x;
    int tid = threadIdx.x;  // 128

    int lo = 0, hi = NN;
    while (lo < hi) { int mid = (lo + hi) >> 1; if (batch[mid] < b) lo = mid + 1; else hi = mid; }
    int start = lo;
    hi = NN;
    while (lo < hi) { int mid = (lo + hi) >> 1; if (batch[mid] < b + 1) lo = mid + 1; else hi = mid; }
    int end = lo;

    __shared__ float red[128];
    float lm = -3.402823466e38f;
    for (int i = start + tid; i < end; i += 128) lm = fmaxf(lm, g[i]);
    red[tid] = lm; __syncthreads();
    for (int s = 64; s; s >>= 1) { if (tid < s) red[tid] = fmaxf(red[tid], red[tid + s]); __syncthreads(); }
    float m = red[0]; __syncthreads();

    float ls = 0.f;
    for (int i = start + tid; i < end; i += 128) ls += expf(g[i] - m);
    red[tid] = ls; __syncthreads();
    for (int s = 64; s; s >>= 1) { if (tid < s) red[tid] += red[tid + s]; __syncthreads(); }
    if (tid == 0) { mOut[b] = m; invOut[b] = 1.f / (red[0] + 1e-10f); }
}

// ---------------- weighted-sum pooling (bandwidth-parallel) ---------------
// 256 nodes per block, 128 threads (thread t owns feature t). Sorted batch
// => few graph boundaries per chunk; flush register acc via atomicAdd.
__global__ void pool_accum_kernel(const float* __restrict__ h,
                                  const float* __restrict__ g,
                                  const int* __restrict__ batch,
                                  const float* __restrict__ mIn,
                                  const float* __restrict__ invIn,
                                  float* __restrict__ emb)
{
    __shared__ float coef[256];
    __shared__ int sbat[256];
    int tid = threadIdx.x;      // 128
    int base = blockIdx.x * 256;
    if (base >= NN) return;

    for (int j = tid; j < 256; j += 128) {
        int i = base + j;
        if (i < NN) {
            int bb = batch[i];
            sbat[j] = bb;
            coef[j] = expf(g[i] - mIn[bb]) * invIn[bb];
        } else {
            sbat[j] = batch[NN - 1];
            coef[j] = 0.f;
        }
    }
    __syncthreads();

    float acc = 0.f;
    int cur = sbat[0];
    int cnt = min(256, NN - base);
#pragma unroll 4
    for (int j = 0; j < 256; j++) {
        if (j >= cnt) break;
        int bb = sbat[j];
        if (bb != cur) {
            atomicAdd(&emb[cur * 128 + tid], acc);
            acc = 0.f;
            cur = bb;
        }
        acc += coef[j] * h[(size_t)(base + j) * 128 + tid];
    }
    atomicAdd(&emb[cur * 128 + tid], acc);
}

// ---------------- head MLP: relu(emb@W1+b1)@W2+b2 ------------------------
__global__ void head_kernel(const float* __restrict__ emb,
                            const float* __restrict__ W1,
                            const float* __restrict__ b1,
                            const float* __restrict__ W2,
                            const float* __restrict__ b2,
                            float* __restrict__ out)
{
    int b = blockIdx.x;
    int tid = threadIdx.x;  // 128
    __shared__ float se[128], st[128];
    se[tid] = emb[b * 128 + tid];
    __syncthreads();
    float acc = b1[tid];
#pragma unroll 8
    for (int k = 0; k < 128; k++) acc += se[k] * W1[k * 128 + tid];
    st[tid] = fmaxf(acc, 0.f);
    __syncthreads();
    if (tid < OUTD) {
        float o = b2[tid];
#pragma unroll 8
        for (int k = 0; k < 128; k++) o += st[k] * W2[k * OUTD + tid];
        out[b * OUTD + tid] = o;
    }
}

// ---------------- launcher ----------------------------------------------
extern "C" void kernel_launch(void* const* d_in, const int* in_sizes, int n_in,
                              void* d_out, int out_size)
{
    const float* x        = (const float*)d_in[0];
    const float* edge_w   = (const float*)d_in[1];
    const float* W_in     = (const float*)d_in[2];
    const float* b_in     = (const float*)d_in[3];
    const float* conv_W   = (const float*)d_in[4];
    const float* conv_b   = (const float*)d_in[5];
    const float* bn_gamma = (const float*)d_in[6];
    const float* bn_beta  = (const float*)d_in[7];
    const float* bn_mean  = (const float*)d_in[8];
    const float* bn_var   = (const float*)d_in[9];
    const float* gate_W   = (const float*)d_in[10];
    const float* gate_b   = (const float*)d_in[11];
    const float* head_W1  = (const float*)d_in[12];
    const float* head_b1  = (const float*)d_in[13];
    const float* head_W2  = (const float*)d_in[14];
    const float* head_b2  = (const float*)d_in[15];
    const int*   er       = (const int*)d_in[16];
    const int*   ec       = (const int*)d_in[17];
    const int*   batch    = (const int*)d_in[18];
    float* out = (float*)d_out;

    float *h, *tmp, *acc, *gate, *emb, *mArr, *invArr;
    cudaGetSymbolAddress((void**)&h,   g_h);
    cudaGetSymbolAddress((void**)&tmp, g_tmp);
    cudaGetSymbolAddress((void**)&acc, g_acc);
    cudaGetSymbolAddress((void**)&gate, g_gate);
    cudaGetSymbolAddress((void**)&emb, g_emb);
    cudaGetSymbolAddress((void**)&mArr, g_m);
    cudaGetSymbolAddress((void**)&invArr, g_invs);

    static int smemSet = 0;
    // setting the attribute every call is cheap and graph-safe (host-side)
    cudaFuncSetAttribute(gemm_tf32_kernel,
                         cudaFuncAttributeMaxDynamicSharedMemorySize, 135168);
    (void)smemSet;

    const int gemmGrid = (NN + 127) / 128;         // 391
    const int scatGrid = (EE * 32 + 255) / 256;    // 75000
    const int gateGrid = (NN * 32 + 255) / 256;    // 6250
    const int poolGrid = (NN + 255) / 256;         // 196

    // input projection + relu
    gemm_tf32_kernel<<<gemmGrid, 256, 135168>>>(x, W_in, b_in, h, NN, 1);

    for (int l = 0; l < LL; l++) {
        gemm_tf32_kernel<<<gemmGrid, 256, 135168>>>(h, conv_W + (size_t)l * HH * HH,
                                                    conv_b + l * HH, tmp, NN, 0);
        cudaMemsetAsync(acc, 0, (size_t)NN * HH * sizeof(float));
        spmm_scatter_kernel<<<scatGrid, 256>>>(tmp, edge_w, er, ec, acc);
        bn_relu_res_kernel<<<1480, 256>>>(h, acc,
                                          bn_gamma + l * HH, bn_beta + l * HH,
                                          bn_mean + l * HH, bn_var + l * HH);
    }

    gate_kernel<<<gateGrid, 256>>>(h, gate_W, gate_b, gate);
    seg_stats_kernel<<<GG, 128>>>(gate, batch, mArr, invArr);
    cudaMemsetAsync(emb, 0, GG * HH * sizeof(float));
    pool_accum_kernel<<<poolGrid, 128>>>(h, gate, batch, mArr, invArr, emb);
    head_kernel<<<GG, 128>>>(emb, head_W1, head_b1, head_W2, head_b2, out);
}

// round 3
// speedup vs baseline: 1.5622x; 1.2098x over previous
#include <cuda_runtime.h>
#include <cuda_bf16.h>
#include <math.h>
#include <stdint.h>

#define NN 50000
#define EE 600000
#define HH 128
#define GG 128
#define LL 3
#define OUTD 16

// ---------------- scratch (device globals; no allocation) ----------------
__device__ __align__(256) float g_h[(size_t)NN * HH];    // node features
__device__ __align__(256) float g_tmp[(size_t)NN * HH];  // dense GEMM output
__device__ __align__(256) float g_gate[NN];              // gate logits
__device__ __align__(256) float g_emb[GG * HH];          // graph embeddings
__device__ __align__(256) float g_m[GG];                 // per-graph max
__device__ __align__(256) float g_invs[GG];              // per-graph 1/sumexp
// CSR scratch
__device__ __align__(256) int   g_rowPtr[NN + 1];
__device__ __align__(256) int   g_cursor[NN];
__device__ __align__(256) int   g_csr_col[EE];
__device__ __align__(256) float g_csr_w[EE];

// ---------------- tf32 helpers ----------------
__device__ __forceinline__ float to_tf32(float x) {
    uint32_t u;
    asm("cvt.rna.tf32.f32 %0, %1;" : "=r"(u) : "f"(x));
    return __uint_as_float(u);
}

__device__ __forceinline__ void mma_tf32(float* c, const uint32_t* a, const uint32_t* b) {
    asm volatile(
        "mma.sync.aligned.m16n8k8.row.col.f32.tf32.tf32.f32 "
        "{%0,%1,%2,%3},{%4,%5,%6,%7},{%8,%9},{%0,%1,%2,%3};"
        : "+f"(c[0]), "+f"(c[1]), "+f"(c[2]), "+f"(c[3])
        : "r"(a[0]), "r"(a[1]), "r"(a[2]), "r"(a[3]), "r"(b[0]), "r"(b[1]));
}

// ---------------- TF32 GEMM: C[n,128] = A[n,128] @ W[128,128] + b --------
// Block tile: 64 rows x 128 cols, K=128 single stage, 2 blocks/SM.
// smem: W [128][136] (69632B) + A [64][132] (33792B) = 103424B.
// Pads chosen so both fragment-load patterns are bank-conflict-free:
//   A: bank = gq*4+tq (SPAD_A=132 -> 132%32=4), bijective over warp quarter
//   W: bank = tq*8+gq (SPAD_W=136 -> 136%32=8), bijective
// 8 warps: wm=wid&1 (rows wm*32), wn=wid>>1 (cols wn*32); 2x4 m16n8k8 tiles.
#define SPAD_A 132
#define SPAD_W 136
#define GEMM_SMEM (128 * SPAD_W * 4 + 64 * SPAD_A * 4)

__global__ void __launch_bounds__(256, 2)
gemm_tf32_kernel(const float* __restrict__ A,
                 const float* __restrict__ W,
                 const float* __restrict__ bias,
                 float* __restrict__ C,
                 int nrows, int doRelu)
{
    extern __shared__ float sm[];
    float* Ws = sm;                      // 128*136
    float* As = sm + 128 * SPAD_W;       // 64*132

    int tid = threadIdx.x;
    int rowBase = blockIdx.x << 6;

    // stage W (k-major [128][128]) -> Ws[k][n], tf32
    const float4* Wg4 = (const float4*)W;
#pragma unroll
    for (int i = tid; i < 4096; i += 256) {
        int r = i >> 5, c4 = (i & 31) << 2;
        float4 v = Wg4[i];
        v.x = to_tf32(v.x); v.y = to_tf32(v.y);
        v.z = to_tf32(v.z); v.w = to_tf32(v.w);
        *(float4*)(Ws + r * SPAD_W + c4) = v;
    }
    // stage A tile (64 rows) -> As[m][k], tf32
    const float4* Ag4 = (const float4*)A;
#pragma unroll
    for (int i = tid; i < 2048; i += 256) {
        int r = i >> 5, c4 = (i & 31) << 2;
        int gr = rowBase + r;
        float4 v = (gr < nrows) ? Ag4[(size_t)gr * 32 + (i & 31)]
                                : make_float4(0.f, 0.f, 0.f, 0.f);
        v.x = to_tf32(v.x); v.y = to_tf32(v.y);
        v.z = to_tf32(v.z); v.w = to_tf32(v.w);
        *(float4*)(As + r * SPAD_A + c4) = v;
    }
    __syncthreads();

    int wid = tid >> 5, lane = tid & 31;
    int wm = wid & 1;             // rows wm*32
    int wn = wid >> 1;            // cols wn*32
    int gq = lane >> 2;           // 0..7
    int tq = lane & 3;            // 0..3

    float acc[2][4][4];
#pragma unroll
    for (int mi = 0; mi < 2; mi++)
#pragma unroll
        for (int ni = 0; ni < 4; ni++)
#pragma unroll
            for (int j = 0; j < 4; j++) acc[mi][ni][j] = 0.f;

#pragma unroll
    for (int k0 = 0; k0 < 128; k0 += 8) {
        uint32_t a[2][4];
#pragma unroll
        for (int mi = 0; mi < 2; mi++) {
            int R = (wm << 5) + (mi << 4);
            a[mi][0] = __float_as_uint(As[(R + gq) * SPAD_A + k0 + tq]);
            a[mi][1] = __float_as_uint(As[(R + gq + 8) * SPAD_A + k0 + tq]);
            a[mi][2] = __float_as_uint(As[(R + gq) * SPAD_A + k0 + tq + 4]);
            a[mi][3] = __float_as_uint(As[(R + gq + 8) * SPAD_A + k0 + tq + 4]);
        }
        uint32_t b[4][2];
#pragma unroll
        for (int ni = 0; ni < 4; ni++) {
            int Cn = (wn << 5) + (ni << 3);
            b[ni][0] = __float_as_uint(Ws[(k0 + tq) * SPAD_W + Cn + gq]);
            b[ni][1] = __float_as_uint(Ws[(k0 + tq + 4) * SPAD_W + Cn + gq]);
        }
#pragma unroll
        for (int mi = 0; mi < 2; mi++)
#pragma unroll
            for (int ni = 0; ni < 4; ni++)
                mma_tf32(acc[mi][ni], a[mi], b[ni]);
    }

    // epilogue: c0=(gq,2tq) c1=(gq,2tq+1) c2=(gq+8,2tq) c3=(gq+8,2tq+1)
#pragma unroll
    for (int mi = 0; mi < 2; mi++) {
        int r0 = rowBase + (wm << 5) + (mi << 4) + gq;
#pragma unroll
        for (int ni = 0; ni < 4; ni++) {
            int col = (wn << 5) + (ni << 3) + (tq << 1);
            float b0 = bias[col], b1 = bias[col + 1];
            float v0 = acc[mi][ni][0] + b0, v1 = acc[mi][ni][1] + b1;
            float v2 = acc[mi][ni][2] + b0, v3 = acc[mi][ni][3] + b1;
            if (doRelu) {
                v0 = fmaxf(v0, 0.f); v1 = fmaxf(v1, 0.f);
                v2 = fmaxf(v2, 0.f); v3 = fmaxf(v3, 0.f);
            }
            if (r0 < nrows)     *(float2*)(C + (size_t)r0 * 128 + col)       = make_float2(v0, v1);
            if (r0 + 8 < nrows) *(float2*)(C + (size_t)(r0 + 8) * 128 + col) = make_float2(v2, v3);
        }
    }
}

// ---------------- CSR build --------------------------------------------
__global__ void deg_kernel(const int* __restrict__ er, int* __restrict__ deg)
{
    int e = blockIdx.x * blockDim.x + threadIdx.x;
    if (e < EE) atomicAdd(&deg[er[e]], 1);
}

// single block, 1024 threads: exclusive scan of deg -> rowPtr, cursor
__global__ void scan_kernel(int* __restrict__ cursor /* in: deg, out: start */,
                            int* __restrict__ rowPtr)
{
    const int PER = (NN + 1023) / 1024;  // 49
    int tid = threadIdx.x;
    int base = tid * PER;

    int s = 0;
    for (int i = 0; i < PER; i++) {
        int idx = base + i;
        if (idx < NN) s += cursor[idx];
    }
    // block exclusive scan of per-thread sums
    int lane = tid & 31, wid = tid >> 5;
    int ws = s;
#pragma unroll
    for (int off = 1; off < 32; off <<= 1) {
        int n = __shfl_up_sync(0xFFFFFFFFu, ws, off);
        if (lane >= off) ws += n;
    }
    __shared__ int wsum[32];
    if (lane == 31) wsum[wid] = ws;
    __syncthreads();
    if (wid == 0) {
        int v = wsum[lane];
#pragma unroll
        for (int off = 1; off < 32; off <<= 1) {
            int n = __shfl_up_sync(0xFFFFFFFFu, v, off);
            if (lane >= off) v += n;
        }
        wsum[lane] = v;
    }
    __syncthreads();
    int offset = ws - s + (wid ? wsum[wid - 1] : 0);

    int run = offset;
    for (int i = 0; i < PER; i++) {
        int idx = base + i;
        if (idx < NN) {
            int v = cursor[idx];
            rowPtr[idx] = run;
            cursor[idx] = run;
            run += v;
        }
    }
    if (tid == 1023) rowPtr[NN] = run;
}

__global__ void fill_kernel(const int* __restrict__ er, const int* __restrict__ ec,
                            const float* __restrict__ ew,
                            int* __restrict__ cursor,
                            int* __restrict__ ccol, float* __restrict__ cw)
{
    int e = blockIdx.x * blockDim.x + threadIdx.x;
    if (e >= EE) return;
    int r = er[e];
    int pos = atomicAdd(&cursor[r], 1);
    ccol[pos] = ec[e];
    cw[pos] = ew[e];
}

// ------- fused SpMM-gather + BN + ReLU + residual (+ optional gate) -------
// one warp per row; lanes own 4 features each (float4 layout).
__global__ void spmm_fused_kernel(const float* __restrict__ hn,
                                  const int* __restrict__ rowPtr,
                                  const int* __restrict__ ccol,
                                  const float* __restrict__ cw,
                                  float* __restrict__ h,
                                  const float* __restrict__ gamma,
                                  const float* __restrict__ beta,
                                  const float* __restrict__ mean,
                                  const float* __restrict__ var,
                                  const float* __restrict__ gateW,
                                  const float* __restrict__ gateB,
                                  float* __restrict__ gateOut,
                                  int doGate)
{
    __shared__ float4 sc4[32], sh4[32];
    if (threadIdx.x < 128) {
        int j = threadIdx.x;
        float s = gamma[j] * rsqrtf(var[j] + 1e-5f);
        ((float*)sc4)[j] = s;
        ((float*)sh4)[j] = beta[j] - mean[j] * s;
    }
    __syncthreads();

    int idx = blockIdx.x * blockDim.x + threadIdx.x;
    int row = idx >> 5;
    int lane = idx & 31;
    if (row >= NN) return;

    int start = rowPtr[row];
    int end = rowPtr[row + 1];

    float4 s = make_float4(0.f, 0.f, 0.f, 0.f);
    const float4* hn4 = (const float4*)hn;
    for (int b0 = start; b0 < end; b0 += 32) {
        int j = b0 + lane;
        int c = (j < end) ? ccol[j] : 0;
        float w = (j < end) ? cw[j] : 0.f;
        int n = min(32, end - b0);
        for (int k = 0; k < n; k++) {
            int ck = __shfl_sync(0xFFFFFFFFu, c, k);
            float wk = __shfl_sync(0xFFFFFFFFu, w, k);
            float4 v = hn4[(size_t)ck * 32 + lane];
            s.x += wk * v.x; s.y += wk * v.y;
            s.z += wk * v.z; s.w += wk * v.w;
        }
    }

    float4 scv = sc4[lane], shv = sh4[lane];
    float4 hv = ((float4*)h)[(size_t)row * 32 + lane];
    hv.x += fmaxf(fmaf(s.x, scv.x, shv.x), 0.f);
    hv.y += fmaxf(fmaf(s.y, scv.y, shv.y), 0.f);
    hv.z += fmaxf(fmaf(s.z, scv.z, shv.z), 0.f);
    hv.w += fmaxf(fmaf(s.w, scv.w, shv.w), 0.f);
    ((float4*)h)[(size_t)row * 32 + lane] = hv;

    if (doGate) {
        float4 gw = ((const float4*)gateW)[lane];
        float d = hv.x * gw.x + hv.y * gw.y + hv.z * gw.z + hv.w * gw.w;
#pragma unroll
        for (int off = 16; off; off >>= 1) d += __shfl_xor_sync(0xFFFFFFFFu, d, off);
        if (lane == 0) gateOut[row] = d + gateB[0];
    }
}

// ---------------- per-graph softmax stats (max, 1/sumexp) ----------------
__global__ void seg_stats_kernel(const float* __restrict__ g,
                                 const int* __restrict__ batch,
                                 float* __restrict__ mOut,
                                 float* __restrict__ invOut)
{
    int b = blockIdx.x;
    int tid = threadIdx.x;  // 128

    int lo = 0, hi = NN;
    while (lo < hi) { int mid = (lo + hi) >> 1; if (batch[mid] < b) lo = mid + 1; else hi = mid; }
    int start = lo;
    hi = NN;
    while (lo < hi) { int mid = (lo + hi) >> 1; if (batch[mid] < b + 1) lo = mid + 1; else hi = mid; }
    int end = lo;

    __shared__ float red[128];
    float lm = -3.402823466e38f;
    for (int i = start + tid; i < end; i += 128) lm = fmaxf(lm, g[i]);
    red[tid] = lm; __syncthreads();
    for (int s = 64; s; s >>= 1) { if (tid < s) red[tid] = fmaxf(red[tid], red[tid + s]); __syncthreads(); }
    float m = red[0]; __syncthreads();

    float ls = 0.f;
    for (int i = start + tid; i < end; i += 128) ls += expf(g[i] - m);
    red[tid] = ls; __syncthreads();
    for (int s = 64; s; s >>= 1) { if (tid < s) red[tid] += red[tid + s]; __syncthreads(); }
    if (tid == 0) { mOut[b] = m; invOut[b] = 1.f / (red[0] + 1e-10f); }
}

// ---------------- weighted-sum pooling (bandwidth-parallel) ---------------
__global__ void pool_accum_kernel(const float* __restrict__ h,
                                  const float* __restrict__ g,
                                  const int* __restrict__ batch,
                                  const float* __restrict__ mIn,
                                  const float* __restrict__ invIn,
                                  float* __restrict__ emb)
{
    __shared__ float coef[256];
    __shared__ int sbat[256];
    int tid = threadIdx.x;      // 128
    int base = blockIdx.x * 256;
    if (base >= NN) return;

    for (int j = tid; j < 256; j += 128) {
        int i = base + j;
        if (i < NN) {
            int bb = batch[i];
            sbat[j] = bb;
            coef[j] = expf(g[i] - mIn[bb]) * invIn[bb];
        } else {
            sbat[j] = batch[NN - 1];
            coef[j] = 0.f;
        }
    }
    __syncthreads();

    float acc = 0.f;
    int cur = sbat[0];
    int cnt = min(256, NN - base);
#pragma unroll 4
    for (int j = 0; j < 256; j++) {
        if (j >= cnt) break;
        int bb = sbat[j];
        if (bb != cur) {
            atomicAdd(&emb[cur * 128 + tid], acc);
            acc = 0.f;
            cur = bb;
        }
        acc += coef[j] * h[(size_t)(base + j) * 128 + tid];
    }
    atomicAdd(&emb[cur * 128 + tid], acc);
}

// ---------------- head MLP: relu(emb@W1+b1)@W2+b2 ------------------------
__global__ void head_kernel(const float* __restrict__ emb,
                            const float* __restrict__ W1,
                            const float* __restrict__ b1,
                            const float* __restrict__ W2,
                            const float* __restrict__ b2,
                            float* __restrict__ out)
{
    int b = blockIdx.x;
    int tid = threadIdx.x;  // 128
    __shared__ float se[128], st[128];
    se[tid] = emb[b * 128 + tid];
    __syncthreads();
    float acc = b1[tid];
#pragma unroll 8
    for (int k = 0; k < 128; k++) acc += se[k] * W1[k * 128 + tid];
    st[tid] = fmaxf(acc, 0.f);
    __syncthreads();
    if (tid < OUTD) {
        float o = b2[tid];
#pragma unroll 8
        for (int k = 0; k < 128; k++) o += st[k] * W2[k * OUTD + tid];
        out[b * OUTD + tid] = o;
    }
}

// ---------------- launcher ----------------------------------------------
extern "C" void kernel_launch(void* const* d_in, const int* in_sizes, int n_in,
                              void* d_out, int out_size)
{
    const float* x        = (const float*)d_in[0];
    const float* edge_w   = (const float*)d_in[1];
    const float* W_in     = (const float*)d_in[2];
    const float* b_in     = (const float*)d_in[3];
    const float* conv_W   = (const float*)d_in[4];
    const float* conv_b   = (const float*)d_in[5];
    const float* bn_gamma = (const float*)d_in[6];
    const float* bn_beta  = (const float*)d_in[7];
    const float* bn_mean  = (const float*)d_in[8];
    const float* bn_var   = (const float*)d_in[9];
    const float* gate_W   = (const float*)d_in[10];
    const float* gate_b   = (const float*)d_in[11];
    const float* head_W1  = (const float*)d_in[12];
    const float* head_b1  = (const float*)d_in[13];
    const float* head_W2  = (const float*)d_in[14];
    const float* head_b2  = (const float*)d_in[15];
    const int*   er       = (const int*)d_in[16];
    const int*   ec       = (const int*)d_in[17];
    const int*   batch    = (const int*)d_in[18];
    float* out = (float*)d_out;

    float *h, *tmp, *gate, *emb, *mArr, *invArr, *cw;
    int *rowPtr, *cursor, *ccol;
    cudaGetSymbolAddress((void**)&h,      g_h);
    cudaGetSymbolAddress((void**)&tmp,    g_tmp);
    cudaGetSymbolAddress((void**)&gate,   g_gate);
    cudaGetSymbolAddress((void**)&emb,    g_emb);
    cudaGetSymbolAddress((void**)&mArr,   g_m);
    cudaGetSymbolAddress((void**)&invArr, g_invs);
    cudaGetSymbolAddress((void**)&rowPtr, g_rowPtr);
    cudaGetSymbolAddress((void**)&cursor, g_cursor);
    cudaGetSymbolAddress((void**)&ccol,   g_csr_col);
    cudaGetSymbolAddress((void**)&cw,     g_csr_w);

    cudaFuncSetAttribute(gemm_tf32_kernel,
                         cudaFuncAttributeMaxDynamicSharedMemorySize, GEMM_SMEM);

    const int gemmGrid = (NN + 63) / 64;           // 782
    const int edgeGrid = (EE + 255) / 256;         // 2344
    const int spmmGrid = (NN * 32 + 255) / 256;    // 6250
    const int poolGrid = (NN + 255) / 256;         // 196

    // ---- CSR build (runs concurrently-ish with first GEMM in stream order) ----
    cudaMemsetAsync(cursor, 0, NN * sizeof(int));
    deg_kernel<<<edgeGrid, 256>>>(er, cursor);
    scan_kernel<<<1, 1024>>>(cursor, rowPtr);
    fill_kernel<<<edgeGrid, 256>>>(er, ec, edge_w, cursor, ccol, cw);

    // ---- input projection + relu ----
    gemm_tf32_kernel<<<gemmGrid, 256, GEMM_SMEM>>>(x, W_in, b_in, h, NN, 1);

    for (int l = 0; l < LL; l++) {
        gemm_tf32_kernel<<<gemmGrid, 256, GEMM_SMEM>>>(h, conv_W + (size_t)l * HH * HH,
                                                       conv_b + l * HH, tmp, NN, 0);
        spmm_fused_kernel<<<spmmGrid, 256>>>(tmp, rowPtr, ccol, cw, h,
                                             bn_gamma + l * HH, bn_beta + l * HH,
                                             bn_mean + l * HH, bn_var + l * HH,
                                             gate_W, gate_b, gate,
                                             (l == LL - 1) ? 1 : 0);
    }

    seg_stats_kernel<<<GG, 128>>>(gate, batch, mArr, invArr);
    cudaMemsetAsync(emb, 0, GG * HH * sizeof(float));
    pool_accum_kernel<<<poolGrid, 128>>>(h, gate, batch, mArr, invArr, emb);
    head_kernel<<<GG, 128>>>(emb, head_W1, head_b1, head_W2, head_b2, out);
}

// round 5
// speedup vs baseline: 1.8903x; 1.2100x over previous
#include <cuda_runtime.h>
#include <cuda_fp16.h>
#include <math.h>
#include <stdint.h>

#define NN 50000
#define EE 600000
#define HH 128
#define GG 128
#define LL 3
#define OUTD 16

// ---------------- scratch (device globals; no allocation) ----------------
__device__ __align__(256) float g_h[(size_t)NN * HH];     // node features (fp32)
__device__ __align__(256) __half g_tmp[(size_t)NN * HH];  // GEMM output (fp16)
__device__ __align__(256) float g_gate[NN];               // gate logits
__device__ __align__(256) float g_emb[GG * HH];           // graph embeddings
__device__ __align__(256) float g_m[GG];                  // per-graph max
__device__ __align__(256) float g_invs[GG];               // per-graph 1/sumexp
__device__ __align__(1024) __half g_wst[4 * 16384];       // transposed fp16 W
// CSR scratch
__device__ __align__(256) int   g_rowPtr[NN + 1];
__device__ __align__(256) int   g_cursor[NN];
__device__ __align__(256) int   g_csr_col[EE];
__device__ __align__(256) float g_csr_w[EE];

// ---------------- fp16 MMA helper ----------------
__device__ __forceinline__ void mma_f16(float* c, const uint32_t* a, const uint32_t* b) {
    asm volatile(
        "mma.sync.aligned.m16n8k16.row.col.f32.f16.f16.f32 "
        "{%0,%1,%2,%3},{%4,%5,%6,%7},{%8,%9},{%0,%1,%2,%3};"
        : "+f"(c[0]), "+f"(c[1]), "+f"(c[2]), "+f"(c[3])
        : "r"(a[0]), "r"(a[1]), "r"(a[2]), "r"(a[3]), "r"(b[0]), "r"(b[1]));
}

__device__ __forceinline__ uint32_t h2_u32(__half2 h) {
    return *reinterpret_cast<uint32_t*>(&h);
}

// ---------------- W prep: transpose + fp16 ----------------
// Wsrc [k][n] -> Wt [n][k] fp16 (B operand for row.col MMA: computes A @ W).
__global__ void prep_w_kernel(const float* __restrict__ W0,
                              const float* __restrict__ Wc,
                              __half* __restrict__ out)
{
    int i = blockIdx.x * blockDim.x + threadIdx.x;  // 0..16383
    if (i >= 16384) return;
    int wsel = i >> 12;
    int j = i & 4095;
    int n = j >> 5;       // 0..127 output row (N dim)
    int k4 = j & 31;      // 0..31 k-group
    const float* W = (wsel == 0) ? W0 : (Wc + (size_t)(wsel - 1) * 16384);
    __half2 p0 = __floats2half2_rn(W[(k4 * 4 + 0) * 128 + n], W[(k4 * 4 + 1) * 128 + n]);
    __half2 p1 = __floats2half2_rn(W[(k4 * 4 + 2) * 128 + n], W[(k4 * 4 + 3) * 128 + n]);
    *(uint2*)(out + (size_t)wsel * 16384 + n * 128 + k4 * 4) =
        make_uint2(h2_u32(p0), h2_u32(p1));
}

// ---------------- fp16 tensor GEMM: C[n,128] = A[n,128] @ W[128,128] + b --
// 64-row tile, 256 threads, 3 CTAs/SM. smem: Wt[128][136]h + A[64][136]h = 52224B.
// Pad 136 halves (272B/row): byte-bank = 4*row + tq (mod 32) -> conflict-free.
// 8 warps: wm=wid&1 rows wm*32, wn=wid>>1 cols wn*32; 2x4 m16n8k16 tiles; 8 k-steps.
#define SPADH 136
#define SPADB (SPADH * 2)
#define GEMM_SMEM_H ((128 * SPADH + 64 * SPADH) * 2)

__global__ void __launch_bounds__(256, 3)
gemm_f16_kernel(const float* __restrict__ A,
                const __half* __restrict__ Wt,
                const float* __restrict__ bias,
                float* __restrict__ Cf,
                __half* __restrict__ Ch,
                int nrows, int doRelu, int outHalf)
{
    extern __shared__ __half smh[];
    __half* Ws = smh;                    // 128 x 136
    __half* As = smh + 128 * SPADH;      // 64 x 136
    char* Wsb = (char*)Ws;
    char* Asb = (char*)As;

    int tid = threadIdx.x;
    int rowBase = blockIdx.x << 6;

    // stage W: straight copy of prepped [n][k] fp16 image into padded smem
    const uint4* Wg = (const uint4*)Wt;
#pragma unroll
    for (int i = tid; i < 2048; i += 256) {
        int r = i >> 4, q = i & 15;
        *(uint4*)(Wsb + r * SPADB + q * 16) = Wg[i];
    }
    // stage A: fp32 -> fp16 convert into padded smem
    const float4* Ag4 = (const float4*)A;
#pragma unroll
    for (int i = tid; i < 2048; i += 256) {
        int r = i >> 5, c4 = i & 31;
        int gr = rowBase + r;
        float4 v = (gr < nrows) ? Ag4[(size_t)gr * 32 + c4]
                                : make_float4(0.f, 0.f, 0.f, 0.f);
        __half2 p0 = __floats2half2_rn(v.x, v.y);
        __half2 p1 = __floats2half2_rn(v.z, v.w);
        *(uint2*)(Asb + r * SPADB + c4 * 8) = make_uint2(h2_u32(p0), h2_u32(p1));
    }
    __syncthreads();

    int wid = tid >> 5, lane = tid & 31;
    int wm = wid & 1;
    int wn = wid >> 1;
    int gq = lane >> 2;
    int tq = lane & 3;

    float acc[2][4][4];
#pragma unroll
    for (int mi = 0; mi < 2; mi++)
#pragma unroll
        for (int ni = 0; ni < 4; ni++)
#pragma unroll
            for (int j = 0; j < 4; j++) acc[mi][ni][j] = 0.f;

#pragma unroll
    for (int s = 0; s < 8; s++) {
        int kb = (s << 4) * 2 + tq * 4;   // byte offset of k0 + 2*tq halves
        uint32_t a[2][4];
#pragma unroll
        for (int mi = 0; mi < 2; mi++) {
            const char* base = Asb + ((wm << 5) + (mi << 4) + gq) * SPADB + kb;
            a[mi][0] = *(const uint32_t*)(base);
            a[mi][1] = *(const uint32_t*)(base + 8 * SPADB);
            a[mi][2] = *(const uint32_t*)(base + 16);
            a[mi][3] = *(const uint32_t*)(base + 8 * SPADB + 16);
        }
        uint32_t b[4][2];
#pragma unroll
        for (int ni = 0; ni < 4; ni++) {
            const char* base = Wsb + ((wn << 5) + (ni << 3) + gq) * SPADB + kb;
            b[ni][0] = *(const uint32_t*)(base);
            b[ni][1] = *(const uint32_t*)(base + 16);
        }
#pragma unroll
        for (int mi = 0; mi < 2; mi++)
#pragma unroll
            for (int ni = 0; ni < 4; ni++)
                mma_f16(acc[mi][ni], a[mi], b[ni]);
    }

    // epilogue: c0=(gq,2tq) c1=(gq,2tq+1) c2=(gq+8,2tq) c3=(gq+8,2tq+1)
#pragma unroll
    for (int mi = 0; mi < 2; mi++) {
        int r0 = rowBase + (wm << 5) + (mi << 4) + gq;
#pragma unroll
        for (int ni = 0; ni < 4; ni++) {
            int col = (wn << 5) + (ni << 3) + (tq << 1);
            float b0 = bias[col], b1 = bias[col + 1];
            float v0 = acc[mi][ni][0] + b0, v1 = acc[mi][ni][1] + b1;
            float v2 = acc[mi][ni][2] + b0, v3 = acc[mi][ni][3] + b1;
            if (doRelu) {
                v0 = fmaxf(v0, 0.f); v1 = fmaxf(v1, 0.f);
                v2 = fmaxf(v2, 0.f); v3 = fmaxf(v3, 0.f);
            }
            if (outHalf) {
                if (r0 < nrows)
                    *(uint32_t*)(Ch + (size_t)r0 * 128 + col) = h2_u32(__floats2half2_rn(v0, v1));
                if (r0 + 8 < nrows)
                    *(uint32_t*)(Ch + (size_t)(r0 + 8) * 128 + col) = h2_u32(__floats2half2_rn(v2, v3));
            } else {
                if (r0 < nrows)     *(float2*)(Cf + (size_t)r0 * 128 + col)       = make_float2(v0, v1);
                if (r0 + 8 < nrows) *(float2*)(Cf + (size_t)(r0 + 8) * 128 + col) = make_float2(v2, v3);
            }
        }
    }
}

// ---------------- CSR build --------------------------------------------
__global__ void deg_kernel(const int* __restrict__ er, int* __restrict__ deg)
{
    int e = blockIdx.x * blockDim.x + threadIdx.x;
    if (e < EE) atomicAdd(&deg[er[e]], 1);
}

__global__ void scan_kernel(int* __restrict__ cursor, int* __restrict__ rowPtr)
{
    const int PER = (NN + 1023) / 1024;
    int tid = threadIdx.x;
    int base = tid * PER;

    int s = 0;
    for (int i = 0; i < PER; i++) {
        int idx = base + i;
        if (idx < NN) s += cursor[idx];
    }
    int lane = tid & 31, wid = tid >> 5;
    int ws = s;
#pragma unroll
    for (int off = 1; off < 32; off <<= 1) {
        int n = __shfl_up_sync(0xFFFFFFFFu, ws, off);
        if (lane >= off) ws += n;
    }
    __shared__ int wsum[32];
    if (lane == 31) wsum[wid] = ws;
    __syncthreads();
    if (wid == 0) {
        int v = wsum[lane];
#pragma unroll
        for (int off = 1; off < 32; off <<= 1) {
            int n = __shfl_up_sync(0xFFFFFFFFu, v, off);
            if (lane >= off) v += n;
        }
        wsum[lane] = v;
    }
    __syncthreads();
    int offset = ws - s + (wid ? wsum[wid - 1] : 0);

    int run = offset;
    for (int i = 0; i < PER; i++) {
        int idx = base + i;
        if (idx < NN) {
            int v = cursor[idx];
            rowPtr[idx] = run;
            cursor[idx] = run;
            run += v;
        }
    }
    if (tid == 1023) rowPtr[NN] = run;
}

__global__ void fill_kernel(const int* __restrict__ er, const int* __restrict__ ec,
                            const float* __restrict__ ew,
                            int* __restrict__ cursor,
                            int* __restrict__ ccol, float* __restrict__ cw)
{
    int e = blockIdx.x * blockDim.x + threadIdx.x;
    if (e >= EE) return;
    int r = er[e];
    int pos = atomicAdd(&cursor[r], 1);
    ccol[pos] = ec[e];
    cw[pos] = ew[e];
}

// ------- fused SpMM-gather(fp16) + BN + ReLU + residual (+opt gate) -------
// one warp per row; lane owns features 4*lane..4*lane+3 (uint2 = 4 halves).
__global__ void spmm_fused_kernel(const __half* __restrict__ hn,
                                  const int* __restrict__ rowPtr,
                                  const int* __restrict__ ccol,
                                  const float* __restrict__ cw,
                                  float* __restrict__ h,
                                  const float* __restrict__ gamma,
                                  const float* __restrict__ beta,
                                  const float* __restrict__ mean,
                                  const float* __restrict__ var,
                                  const float* __restrict__ gateW,
                                  const float* __restrict__ gateB,
                                  float* __restrict__ gateOut,
                                  int doGate)
{
    __shared__ float4 sc4[32], sh4[32];
    if (threadIdx.x < 128) {
        int j = threadIdx.x;
        float s = gamma[j] * rsqrtf(var[j] + 1e-5f);
        ((float*)sc4)[j] = s;
        ((float*)sh4)[j] = beta[j] - mean[j] * s;
    }
    __syncthreads();

    int idx = blockIdx.x * blockDim.x + threadIdx.x;
    int row = idx >> 5;
    int lane = idx & 31;
    if (row >= NN) return;

    int start = rowPtr[row];
    int end = rowPtr[row + 1];

    float4 s = make_float4(0.f, 0.f, 0.f, 0.f);
    const uint2* hn2 = (const uint2*)hn;
#pragma unroll 4
    for (int j = start; j < end; j++) {
        int c = __ldg(&ccol[j]);        // uniform across warp
        float w = __ldg(&cw[j]);
        uint2 u = hn2[(size_t)c * 32 + lane];
        __half2 ha = *reinterpret_cast<__half2*>(&u.x);
        __half2 hb = *reinterpret_cast<__half2*>(&u.y);
        float2 fa = __half22float2(ha);
        float2 fb = __half22float2(hb);
        s.x += w * fa.x; s.y += w * fa.y;
        s.z += w * fb.x; s.w += w * fb.y;
    }

    float4 scv = sc4[lane], shv = sh4[lane];
    float4 hv = ((float4*)h)[(size_t)row * 32 + lane];
    hv.x += fmaxf(fmaf(s.x, scv.x, shv.x), 0.f);
    hv.y += fmaxf(fmaf(s.y, scv.y, shv.y), 0.f);
    hv.z += fmaxf(fmaf(s.z, scv.z, shv.z), 0.f);
    hv.w += fmaxf(fmaf(s.w, scv.w, shv.w), 0.f);
    ((float4*)h)[(size_t)row * 32 + lane] = hv;

    if (doGate) {
        float4 gw = ((const float4*)gateW)[lane];
        float d = hv.x * gw.x + hv.y * gw.y + hv.z * gw.z + hv.w * gw.w;
#pragma unroll
        for (int off = 16; off; off >>= 1) d += __shfl_xor_sync(0xFFFFFFFFu, d, off);
        if (lane == 0) gateOut[row] = d + gateB[0];
    }
}

// ---------------- per-graph softmax stats (max, 1/sumexp) ----------------
__global__ void seg_stats_kernel(const float* __restrict__ g,
                                 const int* __restrict__ batch,
                                 float* __restrict__ mOut,
                                 float* __restrict__ invOut)
{
    int b = blockIdx.x;
    int tid = threadIdx.x;  // 128

    int lo = 0, hi = NN;
    while (lo < hi) { int mid = (lo + hi) >> 1; if (batch[mid] < b) lo = mid + 1; else hi = mid; }
    int start = lo;
    hi = NN;
    while (lo < hi) { int mid = (lo + hi) >> 1; if (batch[mid] < b + 1) lo = mid + 1; else hi = mid; }
    int end = lo;

    __shared__ float red[128];
    float lm = -3.402823466e38f;
    for (int i = start + tid; i < end; i += 128) lm = fmaxf(lm, g[i]);
    red[tid] = lm; __syncthreads();
    for (int s = 64; s; s >>= 1) { if (tid < s) red[tid] = fmaxf(red[tid], red[tid + s]); __syncthreads(); }
    float m = red[0]; __syncthreads();

    float ls = 0.f;
    for (int i = start + tid; i < end; i += 128) ls += expf(g[i] - m);
    red[tid] = ls; __syncthreads();
    for (int s = 64; s; s >>= 1) { if (tid < s) red[tid] += red[tid + s]; __syncthreads(); }
    if (tid == 0) { mOut[b] = m; invOut[b] = 1.f / (red[0] + 1e-10f); }
}

// ---------------- weighted-sum pooling (bandwidth-parallel) ---------------
__global__ void pool_accum_kernel(const float* __restrict__ h,
                                  const float* __restrict__ g,
                                  const int* __restrict__ batch,
                                  const float* __restrict__ mIn,
                                  const float* __restrict__ invIn,
                                  float* __restrict__ emb)
{
    __shared__ float coef[256];
    __shared__ int sbat[256];
    int tid = threadIdx.x;      // 128
    int base = blockIdx.x * 256;
    if (base >= NN) return;

    for (int j = tid; j < 256; j += 128) {
        int i = base + j;
        if (i < NN) {
            int bb = batch[i];
            sbat[j] = bb;
            coef[j] = expf(g[i] - mIn[bb]) * invIn[bb];
        } else {
            sbat[j] = batch[NN - 1];
            coef[j] = 0.f;
        }
    }
    __syncthreads();

    float acc = 0.f;
    int cur = sbat[0];
    int cnt = min(256, NN - base);
#pragma unroll 4
    for (int j = 0; j < 256; j++) {
        if (j >= cnt) break;
        int bb = sbat[j];
        if (bb != cur) {
            atomicAdd(&emb[cur * 128 + tid], acc);
            acc = 0.f;
            cur = bb;
        }
        acc += coef[j] * h[(size_t)(base + j) * 128 + tid];
    }
    atomicAdd(&emb[cur * 128 + tid], acc);
}

// ---------------- head MLP: relu(emb@W1+b1)@W2+b2 ------------------------
__global__ void head_kernel(const float* __restrict__ emb,
                            const float* __restrict__ W1,
                            const float* __restrict__ b1,
                            const float* __restrict__ W2,
                            const float* __restrict__ b2,
                            float* __restrict__ out)
{
    int b = blockIdx.x;
    int tid = threadIdx.x;  // 128
    __shared__ float se[128], st[128];
    se[tid] = emb[b * 128 + tid];
    __syncthreads();
    float acc = b1[tid];
#pragma unroll 8
    for (int k = 0; k < 128; k++) acc += se[k] * W1[k * 128 + tid];
    st[tid] = fmaxf(acc, 0.f);
    __syncthreads();
    if (tid < OUTD) {
        float o = b2[tid];
#pragma unroll 8
        for (int k = 0; k < 128; k++) o += st[k] * W2[k * OUTD + tid];
        out[b * OUTD + tid] = o;
    }
}

// ---------------- launcher ----------------------------------------------
extern "C" void kernel_launch(void* const* d_in, const int* in_sizes, int n_in,
                              void* d_out, int out_size)
{
    const float* x        = (const float*)d_in[0];
    const float* edge_w   = (const float*)d_in[1];
    const float* W_in     = (const float*)d_in[2];
    const float* b_in     = (const float*)d_in[3];
    const float* conv_W   = (const float*)d_in[4];
    const float* conv_b   = (const float*)d_in[5];
    const float* bn_gamma = (const float*)d_in[6];
    const float* bn_beta  = (const float*)d_in[7];
    const float* bn_mean  = (const float*)d_in[8];
    const float* bn_var   = (const float*)d_in[9];
    const float* gate_W   = (const float*)d_in[10];
    const float* gate_b   = (const float*)d_in[11];
    const float* head_W1  = (const float*)d_in[12];
    const float* head_b1  = (const float*)d_in[13];
    const float* head_W2  = (const float*)d_in[14];
    const float* head_b2  = (const float*)d_in[15];
    const int*   er       = (const int*)d_in[16];
    const int*   ec       = (const int*)d_in[17];
    const int*   batch    = (const int*)d_in[18];
    float* out = (float*)d_out;

    float *h, *gate, *emb, *mArr, *invArr, *cw;
    __half *tmp, *wst;
    int *rowPtr, *cursor, *ccol;
    cudaGetSymbolAddress((void**)&h,      g_h);
    cudaGetSymbolAddress((void**)&tmp,    g_tmp);
    cudaGetSymbolAddress((void**)&gate,   g_gate);
    cudaGetSymbolAddress((void**)&emb,    g_emb);
    cudaGetSymbolAddress((void**)&mArr,   g_m);
    cudaGetSymbolAddress((void**)&invArr, g_invs);
    cudaGetSymbolAddress((void**)&rowPtr, g_rowPtr);
    cudaGetSymbolAddress((void**)&cursor, g_cursor);
    cudaGetSymbolAddress((void**)&ccol,   g_csr_col);
    cudaGetSymbolAddress((void**)&cw,     g_csr_w);
    cudaGetSymbolAddress((void**)&wst,    g_wst);

    cudaFuncSetAttribute(gemm_f16_kernel,
                         cudaFuncAttributeMaxDynamicSharedMemorySize, GEMM_SMEM_H);

    const int gemmGrid = (NN + 63) / 64;           // 782
    const int edgeGrid = (EE + 255) / 256;         // 2344
    const int spmmGrid = (NN * 32 + 255) / 256;    // 6250
    const int poolGrid = (NN + 255) / 256;         // 196

    // ---- weight prep + CSR build ----
    prep_w_kernel<<<64, 256>>>(W_in, conv_W, wst);
    cudaMemsetAsync(cursor, 0, NN * sizeof(int));
    deg_kernel<<<edgeGrid, 256>>>(er, cursor);
    scan_kernel<<<1, 1024>>>(cursor, rowPtr);
    fill_kernel<<<edgeGrid, 256>>>(er, ec, edge_w, cursor, ccol, cw);

    // ---- input projection + relu (fp32 out -> h) ----
    gemm_f16_kernel<<<gemmGrid, 256, GEMM_SMEM_H>>>(x, wst, b_in, h, (__half*)0,
                                                    NN, 1, 0);

    for (int l = 0; l < LL; l++) {
        gemm_f16_kernel<<<gemmGrid, 256, GEMM_SMEM_H>>>(
            h, wst + (size_t)(l + 1) * 16384, conv_b + l * HH,
            (float*)0, tmp, NN, 0, 1);
        spmm_fused_kernel<<<spmmGrid, 256>>>(tmp, rowPtr, ccol, cw, h,
                                             bn_gamma + l * HH, bn_beta + l * HH,
                                             bn_mean + l * HH, bn_var + l * HH,
                                             gate_W, gate_b, gate,
                                             (l == LL - 1) ? 1 : 0);
    }

    seg_stats_kernel<<<GG, 128>>>(gate, batch, mArr, invArr);
    cudaMemsetAsync(emb, 0, GG * HH * sizeof(float));
    pool_accum_kernel<<<poolGrid, 128>>>(h, gate, batch, mArr, invArr, emb);
    head_kernel<<<GG, 128>>>(emb, head_W1, head_b1, head_W2, head_b2, out);
}